// round 11
// baseline (speedup 1.0000x reference)
#include <cuda_runtime.h>
#include <cstdint>

#define NCOLS 2048
#define ORDER 8
#define NB    148
#define TPB   512
#define TILE  12
#define NT    5
#define NPAIR 6

typedef unsigned long long ull;

__device__ __forceinline__ ull pack2(float lo, float hi) {
    ull r; asm("mov.b64 %0, {%1, %2};" : "=l"(r) : "f"(lo), "f"(hi)); return r;
}
__device__ __forceinline__ float2 unpack2(ull v) {
    float2 f; asm("mov.b64 {%0, %1}, %2;" : "=f"(f.x), "=f"(f.y) : "l"(v)); return f;
}
__device__ __forceinline__ ull ffma2(ull a, ull b, ull c) {
    ull d; asm("fma.rn.f32x2 %0, %1, %2, %3;" : "=l"(d) : "l"(a), "l"(b), "l"(c)); return d;
}
__device__ __forceinline__ ull fmul2(ull a, ull b) {
    ull d; asm("mul.rn.f32x2 %0, %1, %2;" : "=l"(d) : "l"(a), "l"(b)); return d;
}
__device__ __forceinline__ ull add2(ull a, ull b) {
    ull d; asm("add.rn.f32x2 %0, %1, %2;" : "=l"(d) : "l"(a), "l"(b)); return d;
}
__device__ __forceinline__ uint32_t s2u(const void* p) {
    uint32_t a;
    asm("{ .reg .u64 t; cvta.to.shared.u64 t, %1; cvt.u32.u64 %0, t; }"
        : "=r"(a) : "l"(p));
    return a;
}
__device__ __forceinline__ void cp16(uint32_t dst, const float* src) {
    asm volatile("cp.async.cg.shared.global [%0], [%1], 16;" :: "r"(dst), "l"(src));
}
__device__ __forceinline__ void cp_commit() { asm volatile("cp.async.commit_group;"); }
__device__ __forceinline__ void cp_wait0()  { asm volatile("cp.async.wait_group 0;"); }

// dynamic smem: xbuf[2][TILE][NCOLS] = 196608 bytes
extern __shared__ float xbuf[];

__global__ void __launch_bounds__(TPB, 1) orth_pipe(
    const float* __restrict__ x, const float* __restrict__ v,
    const float* __restrict__ d, const float* __restrict__ bias,
    float* __restrict__ y)
{
    __shared__ float  gpart[16 * 36];
    __shared__ float2 Tneg2[64];              // duplicated (T,T)
    __shared__ ull    asum[16 * 48];          // [warp][pair*8+k] packed pairs
    __shared__ ull    Bpair[NPAIR * 8];       // packed (b0[k],b1[k]) per pair

    const int t = threadIdx.x, lane = t & 31, w = t >> 5;
    const int c0 = t * 4;

    const int bid = blockIdx.x;
    const int nr = (bid < 52) ? 56 : 55;
    const int r0 = (bid < 52) ? bid * 56 : 52 * 56 + (bid - 52) * 55;

    // ---- kick off prefetch of tile 0 immediately ----
    const uint32_t xb_base = s2u(xbuf);
#pragma unroll
    for (int j = 0; j < TILE; ++j) {
        const int rc = (j < nr) ? j : (nr - 1);
        cp16(xb_base + (uint32_t)(j * NCOLS + c0) * 4,
             x + (size_t)(r0 + rc) * NCOLS + c0);
    }
    cp_commit();

    // ---- V slice (transient float4 form for Gram + dup-pack build) ----
    float4 Vf[ORDER];
#pragma unroll
    for (int k = 0; k < ORDER; ++k)
        Vf[k] = *reinterpret_cast<const float4*>(v + k * NCOLS + c0);

    // ================= Prologue: Gram -> Tneg2 =================
    {
        int idx = 0;
#pragma unroll
        for (int i = 0; i < ORDER; ++i) {
#pragma unroll
            for (int k = i; k < ORDER; ++k) {
                float gg = Vf[i].x * Vf[k].x;
                gg = fmaf(Vf[i].y, Vf[k].y, gg);
                gg = fmaf(Vf[i].z, Vf[k].z, gg);
                gg = fmaf(Vf[i].w, Vf[k].w, gg);
#pragma unroll
                for (int m = 16; m >= 1; m >>= 1)
                    gg += __shfl_xor_sync(0xffffffffu, gg, m);
                if (lane == 0) gpart[w * 36 + idx] = gg;
                ++idx;
            }
        }
    }
    __syncthreads();
    if (t < 36) {
        float s = 0.f;
#pragma unroll
        for (int ww = 0; ww < 16; ++ww) s += gpart[ww * 36 + t];
        gpart[t] = s;
    }
    __syncthreads();
    if (t == 0) {
        float Gs[ORDER][ORDER];
        int id2 = 0;
        for (int i = 0; i < ORDER; ++i)
            for (int k = i; k < ORDER; ++k) {
                Gs[i][k] = gpart[id2]; Gs[k][i] = gpart[id2]; ++id2;
            }
        float rn[ORDER];
        for (int i = 0; i < ORDER; ++i) rn[i] = 1.0f / sqrtf(Gs[i][i]);
        float T[ORDER][ORDER];
        for (int i = 0; i < ORDER; ++i)
            for (int k = 0; k < ORDER; ++k) T[i][k] = 0.f;
        for (int i = 0; i < ORDER; ++i) T[i][i] = 2.f;
        for (int c = 1; c < ORDER; ++c)
            for (int r = 0; r < c; ++r) {
                float s = 0.f;
                for (int m = r; m < c; ++m)
                    s += T[r][m] * (Gs[m][c] * rn[m] * rn[c]);
                T[r][c] = -2.f * s;
            }
        for (int i = 0; i < ORDER; ++i)
            for (int k = 0; k < ORDER; ++k) {
                const float tv = -(rn[i] * T[i][k] * rn[k]);
                Tneg2[i * 8 + k] = make_float2(tv, tv);
            }
    }
    __syncthreads();

    // ---- column-duplicated V packs: (v_c, v_c) per column ----
    ull Vd0[ORDER], Vd1[ORDER], Vd2[ORDER], Vd3[ORDER];
#pragma unroll
    for (int k = 0; k < ORDER; ++k) {
        Vd0[k] = pack2(Vf[k].x, Vf[k].x);
        Vd1[k] = pack2(Vf[k].y, Vf[k].y);
        Vd2[k] = pack2(Vf[k].z, Vf[k].z);
        Vd3[k] = pack2(Vf[k].w, Vf[k].w);
    }

    const float4 dv = *reinterpret_cast<const float4*>(d + c0);
    const float4 bv = *reinterpret_cast<const float4*>(bias + c0);
    const ull dd0 = pack2(dv.x, dv.x), dd1 = pack2(dv.y, dv.y);
    const ull dd2 = pack2(dv.z, dv.z), dd3 = pack2(dv.w, dv.w);
    const ull bb0 = pack2(bv.x, bv.x), bb1 = pack2(bv.y, bv.y);
    const ull bb2 = pack2(bv.z, bv.z), bb3 = pack2(bv.w, bv.w);

    // ================= Pipelined main loop =================
#pragma unroll 1
    for (int tt = 0; tt < NT; ++tt) {
        const int buf = tt & 1;

        cp_wait0();
        __syncthreads();               // tile tt visible; prev pass C done

        if (tt + 1 < NT) {
#pragma unroll
            for (int j = 0; j < TILE; ++j) {
                const int jr = (tt + 1) * TILE + j;
                const int rc = (jr < nr) ? jr : (nr - 1);
                cp16(xb_base + (uint32_t)(((1 - buf) * TILE + j) * NCOLS + c0) * 4,
                     x + (size_t)(r0 + rc) * NCOLS + c0);
            }
            cp_commit();
        }

        const float* xs = &xbuf[buf * TILE * NCOLS];

        // ---- pass A: packed pair-row dots + packed folded butterfly ----
#pragma unroll
        for (int pr = 0; pr < NPAIR; ++pr) {
            const float4 xa = *reinterpret_cast<const float4*>(xs + (2 * pr) * NCOLS + c0);
            const float4 xb = *reinterpret_cast<const float4*>(xs + (2 * pr + 1) * NCOLS + c0);
            const ull xc0 = pack2(xa.x, xb.x);
            const ull xc1 = pack2(xa.y, xb.y);
            const ull xc2 = pack2(xa.z, xb.z);
            const ull xc3 = pack2(xa.w, xb.w);
            ull p[8];
#pragma unroll
            for (int k = 0; k < 8; ++k)
                p[k] = ffma2(xc3, Vd3[k],
                       ffma2(xc2, Vd2[k],
                       ffma2(xc1, Vd1[k],
                       fmul2(xc0, Vd0[k]))));
#pragma unroll
            for (int k = 0; k < 8; ++k) {
                p[k] = add2(p[k], __shfl_xor_sync(0xffffffffu, p[k], 16));
                p[k] = add2(p[k], __shfl_xor_sync(0xffffffffu, p[k], 8));
            }
            const bool h4 = (lane & 4) != 0;
            ull q[4];
#pragma unroll
            for (int jj = 0; jj < 4; ++jj) {
                const ull keep = h4 ? p[jj + 4] : p[jj];
                const ull send = h4 ? p[jj] : p[jj + 4];
                q[jj] = add2(keep, __shfl_xor_sync(0xffffffffu, send, 4));
            }
            const bool h2 = (lane & 2) != 0;
            ull r2[2];
#pragma unroll
            for (int jj = 0; jj < 2; ++jj) {
                const ull keep = h2 ? q[jj + 2] : q[jj];
                const ull send = h2 ? q[jj] : q[jj + 2];
                r2[jj] = add2(keep, __shfl_xor_sync(0xffffffffu, send, 2));
            }
            const bool h1 = (lane & 1) != 0;
            const ull keep = h1 ? r2[1] : r2[0];
            const ull send = h1 ? r2[0] : r2[1];
            const ull s = add2(keep, __shfl_xor_sync(0xffffffffu, send, 1));
            if (lane < 8) asum[w * 48 + pr * 8 + lane] = s;
        }
        __syncthreads();

        // ---- pass B: collapse + B = A*Tneg (64 threads, warp-synchronous)
        if (t < 64) {
            const int pair = t >> 3, k = t & 7;
            const int pc = (pair < NPAIR) ? pair : (NPAIR - 1);   // keep lanes active
            ull a = 0ull;                                          // packed (0,0)
#pragma unroll
            for (int ww = 0; ww < 16; ++ww)
                a = add2(a, asum[ww * 48 + pc * 8 + k]);
            ull bk = 0ull;
#pragma unroll
            for (int i = 0; i < 8; ++i) {
                const ull ai = __shfl_sync(0xffffffffu, a, (lane & 24) | i);
                const float2 tv = Tneg2[i * 8 + k];
                bk = ffma2(ai, pack2(tv.x, tv.y), bk);
            }
            if (pair < NPAIR) Bpair[pair * 8 + k] = bk;
        }
        __syncthreads();

        // ---- pass C: packed correction + scale + store ----
#pragma unroll
        for (int pr = 0; pr < NPAIR; ++pr) {
            const int jr0 = tt * TILE + 2 * pr;
            if (jr0 < nr) {
                const float4 xa = *reinterpret_cast<const float4*>(xs + (2 * pr) * NCOLS + c0);
                const float4 xb = *reinterpret_cast<const float4*>(xs + (2 * pr + 1) * NCOLS + c0);
                ull a0 = pack2(xa.x, xb.x);
                ull a1 = pack2(xa.y, xb.y);
                ull a2 = pack2(xa.z, xb.z);
                ull a3 = pack2(xa.w, xb.w);
#pragma unroll
                for (int k = 0; k < 8; ++k) {
                    const ull bk = Bpair[pr * 8 + k];   // Tneg carries the minus
                    a0 = ffma2(bk, Vd0[k], a0);
                    a1 = ffma2(bk, Vd1[k], a1);
                    a2 = ffma2(bk, Vd2[k], a2);
                    a3 = ffma2(bk, Vd3[k], a3);
                }
                a0 = ffma2(a0, dd0, bb0);
                a1 = ffma2(a1, dd1, bb1);
                a2 = ffma2(a2, dd2, bb2);
                a3 = ffma2(a3, dd3, bb3);
                const float2 f0 = unpack2(a0), f1 = unpack2(a1);
                const float2 f2 = unpack2(a2), f3 = unpack2(a3);
                __stcs(reinterpret_cast<float4*>(y + (size_t)(r0 + jr0) * NCOLS + c0),
                       make_float4(f0.x, f1.x, f2.x, f3.x));
                if (jr0 + 1 < nr)
                    __stcs(reinterpret_cast<float4*>(y + (size_t)(r0 + jr0 + 1) * NCOLS + c0),
                           make_float4(f0.y, f1.y, f2.y, f3.y));
            }
        }
    }
}

extern "C" void kernel_launch(void* const* d_in, const int* in_sizes, int n_in,
                              void* d_out, int out_size) {
    const float* x    = (const float*)d_in[0];
    const float* v    = (const float*)d_in[1];
    const float* dvec = (const float*)d_in[2];
    const float* bias = (const float*)d_in[3];
    float* y = (float*)d_out;
    (void)in_sizes; (void)n_in; (void)out_size;

    const int dyn = 2 * TILE * NCOLS * (int)sizeof(float);   // 196608 B
    static int attr_set = 0;
    if (!attr_set) {
        cudaFuncSetAttribute(orth_pipe,
                             cudaFuncAttributeMaxDynamicSharedMemorySize, dyn);
        attr_set = 1;
    }
    orth_pipe<<<NB, TPB, dyn>>>(x, v, dvec, bias, y);
}

// round 12
// speedup vs baseline: 1.3439x; 1.3439x over previous
#include <cuda_runtime.h>
#include <cstdint>

#define NCOLS 2048
#define ORDER 8
#define NB    148
#define TPB   512
#define TILE  8
#define NT    7

typedef unsigned long long ull;

__device__ __forceinline__ ull pack2(float lo, float hi) {
    ull r; asm("mov.b64 %0, {%1, %2};" : "=l"(r) : "f"(lo), "f"(hi)); return r;
}
__device__ __forceinline__ float2 unpack2(ull v) {
    float2 f; asm("mov.b64 {%0, %1}, %2;" : "=f"(f.x), "=f"(f.y) : "l"(v)); return f;
}
__device__ __forceinline__ ull ffma2(ull a, ull b, ull c) {
    ull d; asm("fma.rn.f32x2 %0, %1, %2, %3;" : "=l"(d) : "l"(a), "l"(b), "l"(c)); return d;
}
__device__ __forceinline__ ull fmul2(ull a, ull b) {
    ull d; asm("mul.rn.f32x2 %0, %1, %2;" : "=l"(d) : "l"(a), "l"(b)); return d;
}
__device__ __forceinline__ uint32_t s2u(const void* p) {
    uint32_t a;
    asm("{ .reg .u64 t; cvta.to.shared.u64 t, %1; cvt.u32.u64 %0, t; }"
        : "=r"(a) : "l"(p));
    return a;
}
__device__ __forceinline__ void cp16(uint32_t dst, const float* src) {
    asm volatile("cp.async.cg.shared.global [%0], [%1], 16;" :: "r"(dst), "l"(src));
}
__device__ __forceinline__ void cp_commit() { asm volatile("cp.async.commit_group;"); }
__device__ __forceinline__ void cp_wait0()  { asm volatile("cp.async.wait_group 0;"); }

// dynamic smem: xbuf[2][TILE][NCOLS] = 131072 bytes
extern __shared__ float xbuf[];

__global__ void __launch_bounds__(TPB, 1) orth_pipe(
    const float* __restrict__ x, const float* __restrict__ v,
    const float* __restrict__ d, const float* __restrict__ bias,
    float* __restrict__ y)
{
    __shared__ float gpart[16 * 36];
    __shared__ float Tneg[64];
    __shared__ float asum[16 * 33];        // [warp][rowInTeam(4)*8+k], stride 33
    __shared__ float B2[2 * 4 * 8 * 2];    // duplicated (b,b): [team][row][k]

    const int t = threadIdx.x, lane = t & 31, w = t >> 5;
    const int g = w >> 3, wg = w & 7;      // team, warp-in-team
    const int colA = wg * 128 + lane * 4;  // first half slice
    const int colB = colA + 1024;          // second half slice
    const int cL = t * 4;                  // linear col for cp.async loads

    const int bid = blockIdx.x;
    const int nr = (bid < 52) ? 56 : 55;
    const int r0 = (bid < 52) ? bid * 56 : 52 * 56 + (bid - 52) * 55;

    // ---- kick off prefetch of tile 0 immediately (linear layout) ----
    const uint32_t xb_base = s2u(xbuf);
#pragma unroll
    for (int j = 0; j < TILE; ++j) {
        const int rc = (j < nr) ? j : (nr - 1);
        cp16(xb_base + (uint32_t)(j * NCOLS + cL) * 4,
             x + (size_t)(r0 + rc) * NCOLS + cL);
    }
    cp_commit();

    // ---- V slice: 8 cols/thread, packed (4 ull banks of 8) = 64 regs ----
    ull VA0[ORDER], VA1[ORDER], VB0[ORDER], VB1[ORDER];
#pragma unroll
    for (int k = 0; k < ORDER; ++k) {
        const float4 a = *reinterpret_cast<const float4*>(v + k * NCOLS + colA);
        const float4 b = *reinterpret_cast<const float4*>(v + k * NCOLS + colB);
        VA0[k] = pack2(a.x, a.y); VA1[k] = pack2(a.z, a.w);
        VB0[k] = pack2(b.x, b.y); VB1[k] = pack2(b.z, b.w);
    }

    // ================= Prologue: Gram -> Tneg =================
    {
        int idx = 0;
#pragma unroll
        for (int i = 0; i < ORDER; ++i) {
#pragma unroll
            for (int k = i; k < ORDER; ++k) {
                ull g2 = fmul2(VA0[i], VA0[k]);
                g2 = ffma2(VA1[i], VA1[k], g2);
                g2 = ffma2(VB0[i], VB0[k], g2);
                g2 = ffma2(VB1[i], VB1[k], g2);
                const float2 f = unpack2(g2);
                float gg = f.x + f.y;
#pragma unroll
                for (int m = 16; m >= 1; m >>= 1)
                    gg += __shfl_xor_sync(0xffffffffu, gg, m);
                if (lane == 0) gpart[w * 36 + idx] = gg;
                ++idx;
            }
        }
    }
    __syncthreads();
    if (t < 36) {
        float s = 0.f;
#pragma unroll
        for (int ww = 0; ww < 16; ++ww) s += gpart[ww * 36 + t];
        gpart[t] = 0.5f * s;   // both teams cover the same columns
    }
    __syncthreads();
    if (t == 0) {
        float Gs[ORDER][ORDER];
        int id2 = 0;
        for (int i = 0; i < ORDER; ++i)
            for (int k = i; k < ORDER; ++k) {
                Gs[i][k] = gpart[id2]; Gs[k][i] = gpart[id2]; ++id2;
            }
        float rn[ORDER];
        for (int i = 0; i < ORDER; ++i) rn[i] = 1.0f / sqrtf(Gs[i][i]);
        float T[ORDER][ORDER];
        for (int i = 0; i < ORDER; ++i)
            for (int k = 0; k < ORDER; ++k) T[i][k] = 0.f;
        for (int i = 0; i < ORDER; ++i) T[i][i] = 2.f;
        for (int c = 1; c < ORDER; ++c)
            for (int r = 0; r < c; ++r) {
                float s = 0.f;
                for (int m = r; m < c; ++m)
                    s += T[r][m] * (Gs[m][c] * rn[m] * rn[c]);
                T[r][c] = -2.f * s;
            }
        for (int i = 0; i < ORDER; ++i)
            for (int k = 0; k < ORDER; ++k)
                Tneg[i * 8 + k] = -(rn[i] * T[i][k] * rn[k]);
    }
    __syncthreads();

    const float4 da = *reinterpret_cast<const float4*>(d + colA);
    const float4 db = *reinterpret_cast<const float4*>(d + colB);
    const float4 ba = *reinterpret_cast<const float4*>(bias + colA);
    const float4 bbv = *reinterpret_cast<const float4*>(bias + colB);
    const ull dA0 = pack2(da.x, da.y), dA1 = pack2(da.z, da.w);
    const ull dB0 = pack2(db.x, db.y), dB1 = pack2(db.z, db.w);
    const ull bA0 = pack2(ba.x, ba.y), bA1 = pack2(ba.z, ba.w);
    const ull bB0 = pack2(bbv.x, bbv.y), bB1 = pack2(bbv.z, bbv.w);

    // ================= Pipelined main loop =================
#pragma unroll 1
    for (int tt = 0; tt < NT; ++tt) {
        const int buf = tt & 1;

        cp_wait0();
        __syncthreads();               // tile tt visible; prev pass C done

        if (tt + 1 < NT) {
#pragma unroll
            for (int j = 0; j < TILE; ++j) {
                const int jr = (tt + 1) * TILE + j;
                const int rc = (jr < nr) ? jr : (nr - 1);
                cp16(xb_base + (uint32_t)(((1 - buf) * TILE + j) * NCOLS + cL) * 4,
                     x + (size_t)(r0 + rc) * NCOLS + cL);
            }
            cp_commit();
        }

        const float* xs = &xbuf[buf * TILE * NCOLS];

        // ---- pass A: team g does tile rows {g, g+2, g+4, g+6} ----
#pragma unroll
        for (int rl = 0; rl < 4; ++rl) {
            const int rowl = 2 * rl + g;
            const float4 xa = *reinterpret_cast<const float4*>(xs + rowl * NCOLS + colA);
            const float4 xb = *reinterpret_cast<const float4*>(xs + rowl * NCOLS + colB);
            const ull x01 = pack2(xa.x, xa.y), x23 = pack2(xa.z, xa.w);
            const ull x45 = pack2(xb.x, xb.y), x67 = pack2(xb.z, xb.w);
            float p[8];
#pragma unroll
            for (int k = 0; k < 8; ++k) {
                ull s2 = fmul2(x01, VA0[k]);
                s2 = ffma2(x23, VA1[k], s2);
                s2 = ffma2(x45, VB0[k], s2);
                s2 = ffma2(x67, VB1[k], s2);
                const float2 f = unpack2(s2);
                p[k] = f.x + f.y;
            }
            // folded butterfly: 23 shfl; lanes 0..7 end with total for k=lane
#pragma unroll
            for (int k = 0; k < 8; ++k) {
                p[k] += __shfl_xor_sync(0xffffffffu, p[k], 16);
                p[k] += __shfl_xor_sync(0xffffffffu, p[k], 8);
            }
            const bool h4 = (lane & 4) != 0;
            float q[4];
#pragma unroll
            for (int jj = 0; jj < 4; ++jj) {
                float keep = h4 ? p[jj + 4] : p[jj];
                float send = h4 ? p[jj] : p[jj + 4];
                q[jj] = keep + __shfl_xor_sync(0xffffffffu, send, 4);
            }
            const bool h2 = (lane & 2) != 0;
            float r2[2];
#pragma unroll
            for (int jj = 0; jj < 2; ++jj) {
                float keep = h2 ? q[jj + 2] : q[jj];
                float send = h2 ? q[jj] : q[jj + 2];
                r2[jj] = keep + __shfl_xor_sync(0xffffffffu, send, 2);
            }
            const bool h1 = (lane & 1) != 0;
            float keep = h1 ? r2[1] : r2[0];
            float send = h1 ? r2[0] : r2[1];
            const float s = keep + __shfl_xor_sync(0xffffffffu, send, 1);
            if (lane < 8) asum[w * 33 + rl * 8 + lane] = s;
        }
        __syncthreads();

        // ---- pass B: 64 threads (2 full warps); collapse 8 warps + T' ----
        if (t < 64) {
            const int tg = t >> 5;           // team handled by this warp
            const int row = (t >> 3) & 3, k = t & 7;
            float a = 0.f;
#pragma unroll
            for (int ww = 0; ww < 8; ++ww)
                a += asum[(tg * 8 + ww) * 33 + row * 8 + k];
            float bk = 0.f;
#pragma unroll
            for (int i = 0; i < 8; ++i) {
                const float ai = __shfl_sync(0xffffffffu, a, (lane & 24) | i);
                bk = fmaf(ai, Tneg[i * 8 + k], bk);
            }
            const int o = ((tg * 4 + row) * 8 + k) * 2;
            B2[o] = bk; B2[o + 1] = bk;
        }
        __syncthreads();

        // ---- pass C: team g corrects its own rows ----
#pragma unroll
        for (int rl = 0; rl < 4; ++rl) {
            const int rowl = 2 * rl + g;
            const int jr = tt * TILE + rowl;
            if (jr < nr) {
                const float4 xa = *reinterpret_cast<const float4*>(xs + rowl * NCOLS + colA);
                const float4 xb = *reinterpret_cast<const float4*>(xs + rowl * NCOLS + colB);
                ull a01 = pack2(xa.x, xa.y), a23 = pack2(xa.z, xa.w);
                ull a45 = pack2(xb.x, xb.y), a67 = pack2(xb.z, xb.w);
#pragma unroll
                for (int k = 0; k < 8; ++k) {
                    const ull bk = *reinterpret_cast<const ull*>(
                        &B2[((g * 4 + rl) * 8 + k) * 2]);   // Tneg carries minus
                    a01 = ffma2(bk, VA0[k], a01);
                    a23 = ffma2(bk, VA1[k], a23);
                    a45 = ffma2(bk, VB0[k], a45);
                    a67 = ffma2(bk, VB1[k], a67);
                }
                a01 = ffma2(a01, dA0, bA0);
                a23 = ffma2(a23, dA1, bA1);
                a45 = ffma2(a45, dB0, bB0);
                a67 = ffma2(a67, dB1, bB1);
                const float2 o0 = unpack2(a01), o1 = unpack2(a23);
                const float2 o2 = unpack2(a45), o3 = unpack2(a67);
                __stcs(reinterpret_cast<float4*>(y + (size_t)(r0 + jr) * NCOLS + colA),
                       make_float4(o0.x, o0.y, o1.x, o1.y));
                __stcs(reinterpret_cast<float4*>(y + (size_t)(r0 + jr) * NCOLS + colB),
                       make_float4(o2.x, o2.y, o3.x, o3.y));
            }
        }
    }
}

extern "C" void kernel_launch(void* const* d_in, const int* in_sizes, int n_in,
                              void* d_out, int out_size) {
    const float* x    = (const float*)d_in[0];
    const float* v    = (const float*)d_in[1];
    const float* dvec = (const float*)d_in[2];
    const float* bias = (const float*)d_in[3];
    float* y = (float*)d_out;
    (void)in_sizes; (void)n_in; (void)out_size;

    const int dyn = 2 * TILE * NCOLS * (int)sizeof(float);   // 131072 B
    static int attr_set = 0;
    if (!attr_set) {
        cudaFuncSetAttribute(orth_pipe,
                             cudaFuncAttributeMaxDynamicSharedMemorySize, dyn);
        attr_set = 1;
    }
    orth_pipe<<<NB, TPB, dyn>>>(x, v, dvec, bias, y);
}